// round 1
// baseline (speedup 1.0000x reference)
#include <cuda_runtime.h>

#define NB 4
#define NN 256
#define XD 256
#define ED 128
#define JT 64

// scratch (static device arrays — no allocation allowed)
static __device__ float g_Q[NB * NN * XD];
static __device__ float g_K[NB * NN * XD];
static __device__ float g_Wvx[XD * XD];
static __device__ float g_bvx[XD];
static __device__ float g_Wfold[ED * ED];
static __device__ float g_bfold[ED];

// ---------------------------------------------------------------------------
// prep: fold weight products
//   Wvx   = Wv @ Wxo           (256x256)   newX = x@Wvx + bvx
//   bvx   = bv @ Wxo + bxo
//   Wfold = Wea @ Weo          (128x128)   E2-through-Weo fold
//   bfold = bea @ Weo + beo
// ---------------------------------------------------------------------------
__global__ void prep_kernel(const float* __restrict__ Wv, const float* __restrict__ bv,
                            const float* __restrict__ Wxo, const float* __restrict__ bxo,
                            const float* __restrict__ Wea, const float* __restrict__ bea,
                            const float* __restrict__ Weo, const float* __restrict__ beo) {
    __shared__ float sRow[256];
    int tx = threadIdx.x;
    int blk = blockIdx.x;
    if (blk < 256) {
        // Wvx row a = blk
        sRow[tx] = Wv[blk * 256 + tx];
        __syncthreads();
        float acc = 0.f;
        #pragma unroll 8
        for (int k = 0; k < 256; k++) acc += sRow[k] * Wxo[k * 256 + tx];
        g_Wvx[blk * 256 + tx] = acc;
    } else if (blk < 384) {
        int m = blk - 256;
        sRow[tx] = Wea[m * 256 + tx];
        __syncthreads();
        if (tx < 128) {
            float acc = 0.f;
            #pragma unroll 8
            for (int c = 0; c < 256; c++) acc += sRow[c] * Weo[c * 128 + tx];
            g_Wfold[m * 128 + tx] = acc;
        }
    } else if (blk == 384) {
        float acc = bxo[tx];
        #pragma unroll 8
        for (int k = 0; k < 256; k++) acc += bv[k] * Wxo[k * 256 + tx];
        g_bvx[tx] = acc;
    } else {
        if (tx < 128) {
            float acc = beo[tx];
            #pragma unroll 8
            for (int c = 0; c < 256; c++) acc += bea[c] * Weo[c * 128 + tx];
            g_bfold[tx] = acc;
        }
    }
}

// ---------------------------------------------------------------------------
// qkx: Q = x@Wq+bq, K = x@Wk+bk  (to scratch), newX = x@Wvx + bvx (to out)
// one block handles 4 rows of x; 256 threads = output columns
// ---------------------------------------------------------------------------
__global__ void qkx_kernel(const float* __restrict__ x,
                           const float* __restrict__ Wq, const float* __restrict__ bq,
                           const float* __restrict__ Wk, const float* __restrict__ bk,
                           float* __restrict__ outX) {
    __shared__ float sX[4][256];
    int tx = threadIdx.x;
    int r0 = blockIdx.x * 4;
    #pragma unroll
    for (int r = 0; r < 4; r++) sX[r][tx] = x[(r0 + r) * 256 + tx];
    __syncthreads();
    float aq[4], ak[4], ax[4];
    #pragma unroll
    for (int r = 0; r < 4; r++) { aq[r] = bq[tx]; ak[r] = bk[tx]; ax[r] = g_bvx[tx]; }
    #pragma unroll 4
    for (int k = 0; k < 256; k++) {
        float wq = Wq[k * 256 + tx];
        float wk = Wk[k * 256 + tx];
        float wv = g_Wvx[k * 256 + tx];
        #pragma unroll
        for (int r = 0; r < 4; r++) {
            aq[r] += sX[r][k] * wq;
            ak[r] += sX[r][k] * wk;
            ax[r] += sX[r][k] * wv;
        }
    }
    #pragma unroll
    for (int r = 0; r < 4; r++) {
        g_Q[(r0 + r) * 256 + tx] = aq[r];
        g_K[(r0 + r) * 256 + tx] = ak[r];
        outX[(r0 + r) * 256 + tx] = ax[r];
    }
}

// ---------------------------------------------------------------------------
// edge kernel: per block = (b, i, 64-wide j tile)
//   E1   = e_tile(64x128) @ Wem(128x256) + bem
//   Ymod = Q_i * K_j * (1/sqrt(32)) * (E1 + 1)            [64x256 in smem]
//   newE = Ymod @ Weo(256x128) + e_tile @ Wfold(128x128) + bfold
// ---------------------------------------------------------------------------
#define SMEM_FLOATS (JT * ED + 256 + 2048 + JT * 260)
#define SMEM_BYTES  (SMEM_FLOATS * 4)

__global__ void __launch_bounds__(256, 2)
edge_kernel(const float* __restrict__ e,
            const float* __restrict__ Wem, const float* __restrict__ bem,
            const float* __restrict__ Weo,
            float* __restrict__ outE) {
    extern __shared__ float smem[];
    float* sE = smem;             // 64*128
    float* sQ = sE + JT * ED;     // 256
    float* sB = sQ + 256;         // 2048 (weight staging, reused)
    float* sY = sB + 2048;        // 64*260 (padded)
    const int YP = 260;
    const float SCALE = 0.17677669529663687f; // 1/sqrt(32)

    int tid = threadIdx.x;
    int tx = tid & 31;
    int ty = tid >> 5;
    int j0 = blockIdx.x * JT;
    int i  = blockIdx.y;
    int b  = blockIdx.z;
    int row_bi = b * NN + i;

    sQ[tid] = g_Q[row_bi * 256 + tid];
    // load e tile (64 x 128 fp32) coalesced via float4
    {
        const float4* e4 = (const float4*)(e + ((size_t)row_bi * NN + j0) * ED);
        float4* sE4 = (float4*)sE;
        #pragma unroll
        for (int t = tid; t < JT * ED / 4; t += 256) sE4[t] = e4[t];
    }
    __syncthreads();

    // ---------------- GEMM1: E1 = sE @ Wem  (64x256) ----------------
    float acc[8][8];
    #pragma unroll
    for (int r = 0; r < 8; r++)
        #pragma unroll
        for (int s = 0; s < 8; s++) acc[r][s] = 0.f;

    for (int m0 = 0; m0 < 128; m0 += 8) {
        if (m0) __syncthreads();
        for (int t = tid; t < 8 * 256; t += 256)
            sB[t] = Wem[(m0 + (t >> 8)) * 256 + (t & 255)];
        __syncthreads();
        #pragma unroll
        for (int mm = 0; mm < 8; mm++) {
            float av[8], bw[8];
            #pragma unroll
            for (int r = 0; r < 8; r++) av[r] = sE[(ty + 8 * r) * ED + m0 + mm];
            #pragma unroll
            for (int s = 0; s < 8; s++) bw[s] = sB[mm * 256 + tx + 32 * s];
            #pragma unroll
            for (int r = 0; r < 8; r++)
                #pragma unroll
                for (int s = 0; s < 8; s++) acc[r][s] += av[r] * bw[s];
        }
    }

    // epilogue: Ymod = Qi * Kj * s * (E1 + 1) -> sY
    {
        float bemv[8];
        #pragma unroll
        for (int s = 0; s < 8; s++) bemv[s] = bem[tx + 32 * s];
        const float* Kb = g_K + ((size_t)b * NN + j0) * 256;
        #pragma unroll
        for (int r = 0; r < 8; r++) {
            int jj = ty + 8 * r;
            #pragma unroll
            for (int s = 0; s < 8; s++) {
                int cc = tx + 32 * s;
                float e1 = acc[r][s] + bemv[s];
                sY[jj * YP + cc] = sQ[cc] * Kb[jj * 256 + cc] * SCALE * (e1 + 1.0f);
            }
        }
    }

    // ---------------- GEMM2: newE = sY @ Weo + sE @ Wfold ----------------
    float acc2[8][4];
    #pragma unroll
    for (int r = 0; r < 8; r++)
        #pragma unroll
        for (int s = 0; s < 4; s++) acc2[r][s] = 0.f;

    for (int c0 = 0; c0 < 256; c0 += 8) {
        __syncthreads();   // first iter also guards sY writes vs reads
        for (int t = tid; t < 8 * 128; t += 256)
            sB[t] = Weo[(c0 + (t >> 7)) * 128 + (t & 127)];
        __syncthreads();
        #pragma unroll
        for (int mm = 0; mm < 8; mm++) {
            float av[8], bw[4];
            #pragma unroll
            for (int r = 0; r < 8; r++) av[r] = sY[(ty + 8 * r) * YP + c0 + mm];
            #pragma unroll
            for (int s = 0; s < 4; s++) bw[s] = sB[mm * 128 + tx + 32 * s];
            #pragma unroll
            for (int r = 0; r < 8; r++)
                #pragma unroll
                for (int s = 0; s < 4; s++) acc2[r][s] += av[r] * bw[s];
        }
    }
    for (int m0 = 0; m0 < 128; m0 += 8) {
        __syncthreads();
        for (int t = tid; t < 8 * 128; t += 256)
            sB[t] = g_Wfold[(m0 + (t >> 7)) * 128 + (t & 127)];
        __syncthreads();
        #pragma unroll
        for (int mm = 0; mm < 8; mm++) {
            float av[8], bw[4];
            #pragma unroll
            for (int r = 0; r < 8; r++) av[r] = sE[(ty + 8 * r) * ED + m0 + mm];
            #pragma unroll
            for (int s = 0; s < 4; s++) bw[s] = sB[mm * 128 + tx + 32 * s];
            #pragma unroll
            for (int r = 0; r < 8; r++)
                #pragma unroll
                for (int s = 0; s < 4; s++) acc2[r][s] += av[r] * bw[s];
        }
    }

    // epilogue: write newE
    {
        float bf[4];
        #pragma unroll
        for (int s = 0; s < 4; s++) bf[s] = g_bfold[tx + 32 * s];
        float* oE = outE + ((size_t)row_bi * NN + j0) * ED;
        #pragma unroll
        for (int r = 0; r < 8; r++) {
            int jj = ty + 8 * r;
            #pragma unroll
            for (int s = 0; s < 4; s++)
                oE[jj * ED + tx + 32 * s] = acc2[r][s] + bf[s];
        }
    }
}

// ---------------------------------------------------------------------------
extern "C" void kernel_launch(void* const* d_in, const int* in_sizes, int n_in,
                              void* d_out, int out_size) {
    (void)in_sizes; (void)n_in; (void)out_size;
    const float* x   = (const float*)d_in[0];
    const float* e   = (const float*)d_in[1];
    const float* Wq  = (const float*)d_in[2];
    const float* bq  = (const float*)d_in[3];
    const float* Wk  = (const float*)d_in[4];
    const float* bk  = (const float*)d_in[5];
    const float* Wv  = (const float*)d_in[6];
    const float* bv  = (const float*)d_in[7];
    const float* Wem = (const float*)d_in[8];
    const float* bem = (const float*)d_in[9];
    const float* Wea = (const float*)d_in[10];
    const float* bea = (const float*)d_in[11];
    const float* Wxo = (const float*)d_in[12];
    const float* bxo = (const float*)d_in[13];
    const float* Weo = (const float*)d_in[14];
    const float* beo = (const float*)d_in[15];

    float* outX = (float*)d_out;                 // [4,256,256]
    float* outE = outX + NB * NN * XD;           // [4,256,256,128]

    cudaFuncSetAttribute(edge_kernel,
                         cudaFuncAttributeMaxDynamicSharedMemorySize, SMEM_BYTES);

    prep_kernel<<<386, 256>>>(Wv, bv, Wxo, bxo, Wea, bea, Weo, beo);
    qkx_kernel<<<256, 256>>>(x, Wq, bq, Wk, bk, outX);
    edge_kernel<<<dim3(4, NN, NB), 256, SMEM_BYTES>>>(e, Wem, bem, Weo, outE);
}

// round 3
// speedup vs baseline: 1.0018x; 1.0018x over previous
#include <cuda_runtime.h>

#define NB 4
#define NN 256
#define XD 256
#define ED 128
#define JT 64

// scratch (static device arrays — no allocation allowed)
static __device__ float g_Q[NB * NN * XD];
static __device__ float g_K[NB * NN * XD];
static __device__ float g_Wvx[XD * XD];
static __device__ float g_bvx[XD];
static __device__ float g_Wfold[ED * ED];
static __device__ float g_bfold[ED];

// ---------------------------------------------------------------------------
// prep: fold weight products
//   Wvx   = Wv @ Wxo           (256x256)   newX = x@Wvx + bvx
//   bvx   = bv @ Wxo + bxo
//   Wfold = Wea @ Weo          (128x128)   E2-through-Weo fold
//   bfold = bea @ Weo + beo
// ---------------------------------------------------------------------------
__global__ void prep_kernel(const float* __restrict__ Wv, const float* __restrict__ bv,
                            const float* __restrict__ Wxo, const float* __restrict__ bxo,
                            const float* __restrict__ Wea, const float* __restrict__ bea,
                            const float* __restrict__ Weo, const float* __restrict__ beo) {
    __shared__ float sRow[256];
    int tx = threadIdx.x;
    int blk = blockIdx.x;
    if (blk < 256) {
        // Wvx row a = blk
        sRow[tx] = Wv[blk * 256 + tx];
        __syncthreads();
        float acc = 0.f;
        #pragma unroll 8
        for (int k = 0; k < 256; k++) acc += sRow[k] * Wxo[k * 256 + tx];
        g_Wvx[blk * 256 + tx] = acc;
    } else if (blk < 384) {
        int m = blk - 256;
        sRow[tx] = Wea[m * 256 + tx];
        __syncthreads();
        if (tx < 128) {
            float acc = 0.f;
            #pragma unroll 8
            for (int c = 0; c < 256; c++) acc += sRow[c] * Weo[c * 128 + tx];
            g_Wfold[m * 128 + tx] = acc;
        }
    } else if (blk == 384) {
        float acc = bxo[tx];
        #pragma unroll 8
        for (int k = 0; k < 256; k++) acc += bv[k] * Wxo[k * 256 + tx];
        g_bvx[tx] = acc;
    } else {
        if (tx < 128) {
            float acc = beo[tx];
            #pragma unroll 8
            for (int c = 0; c < 256; c++) acc += bea[c] * Weo[c * 128 + tx];
            g_bfold[tx] = acc;
        }
    }
}

// ---------------------------------------------------------------------------
// qkx: Q = x@Wq+bq, K = x@Wk+bk  (to scratch), newX = x@Wvx + bvx (to out)
// one block handles 4 rows of x; 256 threads = output columns
// ---------------------------------------------------------------------------
__global__ void qkx_kernel(const float* __restrict__ x,
                           const float* __restrict__ Wq, const float* __restrict__ bq,
                           const float* __restrict__ Wk, const float* __restrict__ bk,
                           float* __restrict__ outX) {
    __shared__ float sX[4][256];
    int tx = threadIdx.x;
    int r0 = blockIdx.x * 4;
    #pragma unroll
    for (int r = 0; r < 4; r++) sX[r][tx] = x[(r0 + r) * 256 + tx];
    __syncthreads();
    float aq[4], ak[4], ax[4];
    #pragma unroll
    for (int r = 0; r < 4; r++) { aq[r] = bq[tx]; ak[r] = bk[tx]; ax[r] = g_bvx[tx]; }
    #pragma unroll 4
    for (int k = 0; k < 256; k++) {
        float wq = Wq[k * 256 + tx];
        float wk = Wk[k * 256 + tx];
        float wv = g_Wvx[k * 256 + tx];
        #pragma unroll
        for (int r = 0; r < 4; r++) {
            aq[r] += sX[r][k] * wq;
            ak[r] += sX[r][k] * wk;
            ax[r] += sX[r][k] * wv;
        }
    }
    #pragma unroll
    for (int r = 0; r < 4; r++) {
        g_Q[(r0 + r) * 256 + tx] = aq[r];
        g_K[(r0 + r) * 256 + tx] = ak[r];
        outX[(r0 + r) * 256 + tx] = ax[r];
    }
}

// ---------------------------------------------------------------------------
// edge kernel: per block = (b, i, 64-wide j tile)
//   E1   = e_tile(64x128) @ Wem(128x256) + bem
//   Ymod = Q_i * K_j * (1/sqrt(32)) * (E1 + 1)            [64x256 in smem]
//   newE = Ymod @ Weo(256x128) + e_tile @ Wfold(128x128) + bfold
// ---------------------------------------------------------------------------
#define SMEM_FLOATS (JT * ED + 256 + 2048 + JT * 260)
#define SMEM_BYTES  (SMEM_FLOATS * 4)

__global__ void __launch_bounds__(256, 2)
edge_kernel(const float* __restrict__ e,
            const float* __restrict__ Wem, const float* __restrict__ bem,
            const float* __restrict__ Weo,
            float* __restrict__ outE) {
    extern __shared__ float smem[];
    float* sE = smem;             // 64*128
    float* sQ = sE + JT * ED;     // 256
    float* sB = sQ + 256;         // 2048 (weight staging, reused)
    float* sY = sB + 2048;        // 64*260 (padded)
    const int YP = 260;
    const float SCALE = 0.17677669529663687f; // 1/sqrt(32)

    int tid = threadIdx.x;
    int tx = tid & 31;
    int ty = tid >> 5;
    int j0 = blockIdx.x * JT;
    int i  = blockIdx.y;
    int b  = blockIdx.z;
    int row_bi = b * NN + i;

    sQ[tid] = g_Q[row_bi * 256 + tid];
    // load e tile (64 x 128 fp32) coalesced via float4
    {
        const float4* e4 = (const float4*)(e + ((size_t)row_bi * NN + j0) * ED);
        float4* sE4 = (float4*)sE;
        #pragma unroll
        for (int t = tid; t < JT * ED / 4; t += 256) sE4[t] = e4[t];
    }
    __syncthreads();

    // ---------------- GEMM1: E1 = sE @ Wem  (64x256) ----------------
    float acc[8][8];
    #pragma unroll
    for (int r = 0; r < 8; r++)
        #pragma unroll
        for (int s = 0; s < 8; s++) acc[r][s] = 0.f;

    for (int m0 = 0; m0 < 128; m0 += 8) {
        if (m0) __syncthreads();
        for (int t = tid; t < 8 * 256; t += 256)
            sB[t] = Wem[(m0 + (t >> 8)) * 256 + (t & 255)];
        __syncthreads();
        #pragma unroll
        for (int mm = 0; mm < 8; mm++) {
            float av[8], bw[8];
            #pragma unroll
            for (int r = 0; r < 8; r++) av[r] = sE[(ty + 8 * r) * ED + m0 + mm];
            #pragma unroll
            for (int s = 0; s < 8; s++) bw[s] = sB[mm * 256 + tx + 32 * s];
            #pragma unroll
            for (int r = 0; r < 8; r++)
                #pragma unroll
                for (int s = 0; s < 8; s++) acc[r][s] += av[r] * bw[s];
        }
    }

    // epilogue: Ymod = Qi * Kj * s * (E1 + 1) -> sY
    {
        float bemv[8];
        #pragma unroll
        for (int s = 0; s < 8; s++) bemv[s] = bem[tx + 32 * s];
        const float* Kb = g_K + ((size_t)b * NN + j0) * 256;
        #pragma unroll
        for (int r = 0; r < 8; r++) {
            int jj = ty + 8 * r;
            #pragma unroll
            for (int s = 0; s < 8; s++) {
                int cc = tx + 32 * s;
                float e1 = acc[r][s] + bemv[s];
                sY[jj * YP + cc] = sQ[cc] * Kb[jj * 256 + cc] * SCALE * (e1 + 1.0f);
            }
        }
    }

    // ---------------- GEMM2: newE = sY @ Weo + sE @ Wfold ----------------
    float acc2[8][4];
    #pragma unroll
    for (int r = 0; r < 8; r++)
        #pragma unroll
        for (int s = 0; s < 4; s++) acc2[r][s] = 0.f;

    for (int c0 = 0; c0 < 256; c0 += 8) {
        __syncthreads();   // first iter also guards sY writes vs reads
        for (int t = tid; t < 8 * 128; t += 256)
            sB[t] = Weo[(c0 + (t >> 7)) * 128 + (t & 127)];
        __syncthreads();
        #pragma unroll
        for (int mm = 0; mm < 8; mm++) {
            float av[8], bw[4];
            #pragma unroll
            for (int r = 0; r < 8; r++) av[r] = sY[(ty + 8 * r) * YP + c0 + mm];
            #pragma unroll
            for (int s = 0; s < 4; s++) bw[s] = sB[mm * 128 + tx + 32 * s];
            #pragma unroll
            for (int r = 0; r < 8; r++)
                #pragma unroll
                for (int s = 0; s < 4; s++) acc2[r][s] += av[r] * bw[s];
        }
    }
    for (int m0 = 0; m0 < 128; m0 += 8) {
        __syncthreads();
        for (int t = tid; t < 8 * 128; t += 256)
            sB[t] = g_Wfold[(m0 + (t >> 7)) * 128 + (t & 127)];
        __syncthreads();
        #pragma unroll
        for (int mm = 0; mm < 8; mm++) {
            float av[8], bw[4];
            #pragma unroll
            for (int r = 0; r < 8; r++) av[r] = sE[(ty + 8 * r) * ED + m0 + mm];
            #pragma unroll
            for (int s = 0; s < 4; s++) bw[s] = sB[mm * 128 + tx + 32 * s];
            #pragma unroll
            for (int r = 0; r < 8; r++)
                #pragma unroll
                for (int s = 0; s < 4; s++) acc2[r][s] += av[r] * bw[s];
        }
    }

    // epilogue: write newE
    {
        float bf[4];
        #pragma unroll
        for (int s = 0; s < 4; s++) bf[s] = g_bfold[tx + 32 * s];
        float* oE = outE + ((size_t)row_bi * NN + j0) * ED;
        #pragma unroll
        for (int r = 0; r < 8; r++) {
            int jj = ty + 8 * r;
            #pragma unroll
            for (int s = 0; s < 4; s++)
                oE[jj * ED + tx + 32 * s] = acc2[r][s] + bf[s];
        }
    }
}

// ---------------------------------------------------------------------------
extern "C" void kernel_launch(void* const* d_in, const int* in_sizes, int n_in,
                              void* d_out, int out_size) {
    (void)in_sizes; (void)n_in; (void)out_size;
    const float* x   = (const float*)d_in[0];
    const float* e   = (const float*)d_in[1];
    const float* Wq  = (const float*)d_in[2];
    const float* bq  = (const float*)d_in[3];
    const float* Wk  = (const float*)d_in[4];
    const float* bk  = (const float*)d_in[5];
    const float* Wv  = (const float*)d_in[6];
    const float* bv  = (const float*)d_in[7];
    const float* Wem = (const float*)d_in[8];
    const float* bem = (const float*)d_in[9];
    const float* Wea = (const float*)d_in[10];
    const float* bea = (const float*)d_in[11];
    const float* Wxo = (const float*)d_in[12];
    const float* bxo = (const float*)d_in[13];
    const float* Weo = (const float*)d_in[14];
    const float* beo = (const float*)d_in[15];

    float* outX = (float*)d_out;                 // [4,256,256]
    float* outE = outX + NB * NN * XD;           // [4,256,256,128]

    cudaFuncSetAttribute(edge_kernel,
                         cudaFuncAttributeMaxDynamicSharedMemorySize, SMEM_BYTES);

    prep_kernel<<<386, 256>>>(Wv, bv, Wxo, bxo, Wea, bea, Weo, beo);
    qkx_kernel<<<256, 256>>>(x, Wq, bq, Wk, bk, outX);
    edge_kernel<<<dim3(4, NN, NB), 256, SMEM_BYTES>>>(e, Wem, bem, Weo, outE);
}